// round 17
// baseline (speedup 1.0000x reference)
#include <cuda_runtime.h>
#include <cstdint>

// Round 16: champion config + final micro-polish.
// Mainloop = R7/R15 (best measured: ~41.1-41.5us, 6.55-6.62TB/s, ~83% DRAM):
// 2x(float4+int4) per thread-step, 32B/lane contiguity, grid-stride lockstep,
// 48 warps/SM, __ldcs both streams, memset-node zeroing.
// Tweaks: red.global.add (no-return) for the final accumulate; index hoisted.
// Predict dur 43.07 -> 42.8-43.1 (noise-level).

__device__ __forceinline__ float bce_w(float x, int h, int mid, float t) {
    float ax  = fabsf(x);
    float e   = __expf(-ax);
    float sp  = __logf(1.0f + e);             // log1p(exp(-|x|)), e in (0,1]
    float bce = fmaxf(x, 0.0f) - x * t + sp;
    return (h >= mid) ? (bce + bce) : bce;    // weight 2 or 1
}

__device__ __forceinline__ void red_add_f32(float* p, float v) {
    asm volatile("red.global.add.f32 [%0], %1;" :: "l"(p), "f"(v) : "memory");
}

__global__ __launch_bounds__(256, 6)
void rw_loss_kernel(const float4* __restrict__ x4,
                    const int4*  __restrict__ h4,
                    const int*   __restrict__ target_p,
                    const int*   __restrict__ H_p,
                    float*       __restrict__ out,
                    int nvec4, float inv_n) {
    const float t   = (float)(*target_p);
    const int   mid = (*H_p) >> 1;

    const int step = gridDim.x * blockDim.x * 2;   // in float4 units
    float acc = 0.0f;

    // Each step handles 8 elements: float4 pair at base, base+1
    // (32B contiguous per thread per stream). 4 independent LDG.128 up front.
    for (int base = (blockIdx.x * blockDim.x + threadIdx.x) * 2;
         base < nvec4; base += step) {
        float4 a0 = __ldcs(&x4[base]);
        float4 a1 = __ldcs(&x4[base + 1]);
        int4   b0 = __ldcs(&h4[base]);
        int4   b1 = __ldcs(&h4[base + 1]);

        acc += bce_w(a0.x, b0.x, mid, t);
        acc += bce_w(a0.y, b0.y, mid, t);
        acc += bce_w(a0.z, b0.z, mid, t);
        acc += bce_w(a0.w, b0.w, mid, t);
        acc += bce_w(a1.x, b1.x, mid, t);
        acc += bce_w(a1.y, b1.y, mid, t);
        acc += bce_w(a1.z, b1.z, mid, t);
        acc += bce_w(a1.w, b1.w, mid, t);
    }

    // warp reduction
    #pragma unroll
    for (int off = 16; off > 0; off >>= 1)
        acc += __shfl_xor_sync(0xFFFFFFFF, acc, off);

    __shared__ float warp_sums[8];
    const int lane = threadIdx.x & 31;
    const int wid  = threadIdx.x >> 5;
    if (lane == 0) warp_sums[wid] = acc;
    __syncthreads();

    if (wid == 0) {
        float v = (lane < 8) ? warp_sums[lane] : 0.0f;
        #pragma unroll
        for (int off = 4; off > 0; off >>= 1)
            v += __shfl_xor_sync(0xFFFFFFFF, v, off);
        if (lane == 0)
            red_add_f32(out, v * inv_n);   // no-return reduction
    }
}

extern "C" void kernel_launch(void* const* d_in, const int* in_sizes, int n_in,
                              void* d_out, int out_size) {
    const float* x      = (const float*)d_in[0];   // logits, N fp32
    const int*   target = (const int*)d_in[1];     // scalar int
    const int*   hidx   = (const int*)d_in[2];     // height_indices, N int32
    const int*   Hp     = (const int*)d_in[3];     // scalar int
    float* out = (float*)d_out;

    const int n = in_sizes[0];
    const int nvec4 = n / 4;   // float4 count (N divisible by 8)
    const float inv_n = 1.0f / (float)n;

    // Zero the accumulator via a memset node (cheaper than a kernel launch).
    cudaMemsetAsync(out, 0, sizeof(float), 0);

    const int threads = 256;
    const int blocks  = 888;  // 148 SMs * 6
    rw_loss_kernel<<<blocks, threads>>>(
        (const float4*)x, (const int4*)hidx, target, Hp, out, nvec4, inv_n);
}